// round 5
// baseline (speedup 1.0000x reference)
#include <cuda_runtime.h>

// Problem-fixed maxima (from reference: N_VERTS=100000, N_EDGES=3200000)
#define NV_MAX 100000
#define E_MAX  3200000

// Scratch (static __device__ — allocation is forbidden)
__device__ float  g_metric[NV_MAX * 12];   // 9 floats padded to 12 (3x float4)
__device__ float4 g_verts [NV_MAX];        // xyz padded to float4
__device__ float  g_row_sum[NV_MAX];
__device__ float  g_col_sum[NV_MAX];
__device__ float  g_w[E_MAX];

// ---------------------------------------------------------------------------
__global__ void zero_sums_kernel(int n) {
    int i = blockIdx.x * blockDim.x + threadIdx.x;
    if (i < n) { g_row_sum[i] = 0.f; g_col_sum[i] = 0.f; }
}

// ---------------------------------------------------------------------------
// Per-vertex MLP: h = relu(f @ W1 + b1); m = h @ W2 + b2  (64 -> 32 -> 9)
// One block = 128 vertices. Feature tile staged in shared (coalesced),
// bank-conflict-free via stride-65 padding.
__global__ __launch_bounds__(128) void mlp_kernel(
    const float* __restrict__ features,
    const float* __restrict__ vertices,
    const float* __restrict__ W1,
    const float* __restrict__ b1,
    const float* __restrict__ W2,
    const float* __restrict__ b2,
    int n)
{
    __shared__ float feat_s[128 * 65];
    __shared__ float W1s[64 * 32];
    __shared__ float W2s[32 * 9];
    __shared__ float b1s[32];
    __shared__ float b2s[9];

    const int t  = threadIdx.x;
    const int v0 = blockIdx.x * 128;

    for (int i = t; i < 64 * 32; i += 128) W1s[i] = W1[i];
    for (int i = t; i < 32 * 9;  i += 128) W2s[i] = W2[i];
    if (t < 32) b1s[t] = b1[t];
    if (t < 9)  b2s[t] = b2[t];

    // Cooperative coalesced float4 load of the 128x64 feature tile
    int nv = n - v0; if (nv > 128) nv = 128;
    const float4* fsrc = (const float4*)(features + (size_t)v0 * 64);
    int n4 = nv * 16;  // float4s in tile
    for (int i = t; i < n4; i += 128) {
        float4 f = fsrc[i];
        int row = i >> 4;
        int col = (i & 15) * 4;
        float* dstp = &feat_s[row * 65 + col];
        dstp[0] = f.x; dstp[1] = f.y; dstp[2] = f.z; dstp[3] = f.w;
    }
    __syncthreads();

    int v = v0 + t;
    if (v >= n) return;

    float h[32];
    #pragma unroll
    for (int j = 0; j < 32; j++) h[j] = b1s[j];

    const float* fr = &feat_s[t * 65];
    #pragma unroll 4
    for (int k = 0; k < 64; k++) {
        float fk = fr[k];
        #pragma unroll
        for (int j = 0; j < 32; j++) h[j] = fmaf(fk, W1s[k * 32 + j], h[j]);
    }
    #pragma unroll
    for (int j = 0; j < 32; j++) h[j] = fmaxf(h[j], 0.f);

    float m[9];
    #pragma unroll
    for (int c = 0; c < 9; c++) m[c] = b2s[c];
    #pragma unroll
    for (int j = 0; j < 32; j++) {
        float hj = h[j];
        #pragma unroll
        for (int c = 0; c < 9; c++) m[c] = fmaf(hj, W2s[j * 9 + c], m[c]);
    }

    float4* mp = (float4*)&g_metric[(size_t)v * 12];
    mp[0] = make_float4(m[0], m[1], m[2], m[3]);
    mp[1] = make_float4(m[4], m[5], m[6], m[7]);
    mp[2] = make_float4(m[8], 0.f, 0.f, 0.f);

    g_verts[v] = make_float4(vertices[(size_t)v * 3 + 0],
                             vertices[(size_t)v * 3 + 1],
                             vertices[(size_t)v * 3 + 2], 0.f);
}

// ---------------------------------------------------------------------------
// Edge pass 1: w = 1/(1 + |M[src] @ (v[dst]-v[src])|^2); scatter-add degrees.
__global__ __launch_bounds__(256) void edge_pass1_kernel(
    const int* __restrict__ src, const int* __restrict__ dst, int e)
{
    int i = blockIdx.x * blockDim.x + threadIdx.x;
    if (i >= e) return;
    int s = src[i];
    int d = dst[i];

    float4 vs = g_verts[s];
    float4 vd = g_verts[d];
    float tx = vd.x - vs.x, ty = vd.y - vs.y, tz = vd.z - vs.z;

    const float4* mp = (const float4*)&g_metric[(size_t)s * 12];
    float4 m0 = mp[0], m1 = mp[1], m2 = mp[2];

    float d0 = fmaf(m0.x, tx, fmaf(m0.y, ty, m0.z * tz));
    float d1 = fmaf(m0.w, tx, fmaf(m1.x, ty, m1.y * tz));
    float d2 = fmaf(m1.z, tx, fmaf(m1.w, ty, m2.x * tz));

    float dist2 = fmaf(d0, d0, fmaf(d1, d1, d2 * d2));
    float w = 1.f / (1.f + dist2);

    g_w[i] = w;
    atomicAdd(&g_row_sum[s], w);
    atomicAdd(&g_col_sum[d], w);
}

// ---------------------------------------------------------------------------
// Edge pass 2: normalize + emit COO. mode 0: [rows|cols|values] (6E floats).
// mode 1: values only (2E floats).
__global__ __launch_bounds__(256) void edge_pass2_kernel(
    const int* __restrict__ src, const int* __restrict__ dst,
    float* __restrict__ out, int e, int mode)
{
    int i = blockIdx.x * blockDim.x + threadIdx.x;
    if (i >= e) return;
    int s = src[i];
    int d = dst[i];
    float w  = g_w[i];
    float rs = g_row_sum[s];
    float cs = g_col_sum[d];
    float v_row = 0.5f * w / rs;
    float v_col = 0.5f * w / cs;

    size_t E = (size_t)e;
    if (mode == 0) {
        // indices row 0 (rows): [src, dst]
        out[i]         = (float)s;
        out[E + i]     = (float)d;
        // indices row 1 (cols): [dst, src]
        out[2 * E + i] = (float)d;
        out[3 * E + i] = (float)s;
        // values: 0.5*[w_row, w_col]
        out[4 * E + i] = v_row;
        out[5 * E + i] = v_col;
    } else {
        out[i]     = v_row;
        out[E + i] = v_col;
    }
}

// ---------------------------------------------------------------------------
extern "C" void kernel_launch(void* const* d_in, const int* in_sizes, int n_in,
                              void* d_out, int out_size)
{
    const float* features = (const float*)d_in[0];
    const float* vertices = (const float*)d_in[1];
    const float* W1       = (const float*)d_in[2];
    const float* b1       = (const float*)d_in[3];
    const float* W2       = (const float*)d_in[4];
    const float* b2       = (const float*)d_in[5];
    const int*   edges    = (const int*)  d_in[6];

    int n = in_sizes[1] / 3;   // vertices: (N, 3)
    int e = in_sizes[6] / 2;   // edges: (2, E)
    const int* src = edges;
    const int* dst = edges + e;
    float* out = (float*)d_out;

    int mode = (out_size == 2 * e) ? 1 : 0;  // default: full [rows|cols|values]

    zero_sums_kernel<<<(n + 255) / 256, 256>>>(n);
    mlp_kernel<<<(n + 127) / 128, 128>>>(features, vertices, W1, b1, W2, b2, n);
    edge_pass1_kernel<<<(e + 255) / 256, 256>>>(src, dst, e);
    edge_pass2_kernel<<<(e + 255) / 256, 256>>>(src, dst, out, e, mode);
}

// round 6
// speedup vs baseline: 1.0130x; 1.0130x over previous
#include <cuda_runtime.h>

// Problem-fixed maxima (N_VERTS=100000, N_EDGES=3200000)
#define NV_MAX 100000
#define E_MAX  3200000

// Scratch (static __device__ — allocation is forbidden)
__device__ float4 g_G[NV_MAX * 2];        // Gram matrix MᵀM: {Gxx,Gyy,Gzz,Gxy},{Gxz,Gyz,-,-}
__device__ float4 g_verts[NV_MAX];        // xyz padded to float4
__device__ float  g_row_sum[NV_MAX];
__device__ float  g_col_sum[NV_MAX];
__device__ float  g_w[E_MAX];

// ---------------------------------------------------------------------------
__global__ void zero_sums_kernel(int n) {
    int i = blockIdx.x * blockDim.x + threadIdx.x;
    if (i < n) { g_row_sum[i] = 0.f; g_col_sum[i] = 0.f; }
}

// ---------------------------------------------------------------------------
// After pass1: turn sums into 0.5/sum so pass2 is multiply-only.
__global__ void inv_sums_kernel(int n) {
    int i = blockIdx.x * blockDim.x + threadIdx.x;
    if (i < n) {
        g_row_sum[i] = 0.5f / g_row_sum[i];
        g_col_sum[i] = 0.5f / g_col_sum[i];
    }
}

// ---------------------------------------------------------------------------
// Per-vertex MLP: h = relu(f @ W1 + b1); M = h @ W2 + b2 (64 -> 32 -> 9),
// then emit G = MᵀM (symmetric, 6 unique floats) + padded vertex.
__global__ __launch_bounds__(128) void mlp_kernel(
    const float* __restrict__ features,
    const float* __restrict__ vertices,
    const float* __restrict__ W1,
    const float* __restrict__ b1,
    const float* __restrict__ W2,
    const float* __restrict__ b2,
    int n)
{
    __shared__ float feat_s[128 * 65];
    __shared__ float W1s[64 * 32];
    __shared__ float W2s[32 * 9];
    __shared__ float b1s[32];
    __shared__ float b2s[9];

    const int t  = threadIdx.x;
    const int v0 = blockIdx.x * 128;

    for (int i = t; i < 64 * 32; i += 128) W1s[i] = W1[i];
    for (int i = t; i < 32 * 9;  i += 128) W2s[i] = W2[i];
    if (t < 32) b1s[t] = b1[t];
    if (t < 9)  b2s[t] = b2[t];

    // Coalesced float4 load of the 128x64 feature tile (stride-65 to kill conflicts)
    int nv = n - v0; if (nv > 128) nv = 128;
    const float4* fsrc = (const float4*)(features + (size_t)v0 * 64);
    int n4 = nv * 16;
    for (int i = t; i < n4; i += 128) {
        float4 f = fsrc[i];
        int row = i >> 4;
        int col = (i & 15) * 4;
        float* dstp = &feat_s[row * 65 + col];
        dstp[0] = f.x; dstp[1] = f.y; dstp[2] = f.z; dstp[3] = f.w;
    }
    __syncthreads();

    int v = v0 + t;
    if (v >= n) return;

    float h[32];
    #pragma unroll
    for (int j = 0; j < 32; j++) h[j] = b1s[j];

    const float* fr = &feat_s[t * 65];
    #pragma unroll 4
    for (int k = 0; k < 64; k++) {
        float fk = fr[k];
        #pragma unroll
        for (int j = 0; j < 32; j++) h[j] = fmaf(fk, W1s[k * 32 + j], h[j]);
    }
    #pragma unroll
    for (int j = 0; j < 32; j++) h[j] = fmaxf(h[j], 0.f);

    float m[9];
    #pragma unroll
    for (int c = 0; c < 9; c++) m[c] = b2s[c];
    #pragma unroll
    for (int j = 0; j < 32; j++) {
        float hj = h[j];
        #pragma unroll
        for (int c = 0; c < 9; c++) m[c] = fmaf(hj, W2s[j * 9 + c], m[c]);
    }

    // G = MᵀM (rows of M are m[3i..3i+2])
    float Gxx = fmaf(m[0], m[0], fmaf(m[3], m[3], m[6] * m[6]));
    float Gyy = fmaf(m[1], m[1], fmaf(m[4], m[4], m[7] * m[7]));
    float Gzz = fmaf(m[2], m[2], fmaf(m[5], m[5], m[8] * m[8]));
    float Gxy = fmaf(m[0], m[1], fmaf(m[3], m[4], m[6] * m[7]));
    float Gxz = fmaf(m[0], m[2], fmaf(m[3], m[5], m[6] * m[8]));
    float Gyz = fmaf(m[1], m[2], fmaf(m[4], m[5], m[7] * m[8]));

    g_G[(size_t)v * 2 + 0] = make_float4(Gxx, Gyy, Gzz, Gxy);
    g_G[(size_t)v * 2 + 1] = make_float4(Gxz, Gyz, 0.f, 0.f);

    g_verts[v] = make_float4(vertices[(size_t)v * 3 + 0],
                             vertices[(size_t)v * 3 + 1],
                             vertices[(size_t)v * 3 + 2], 0.f);
}

// ---------------------------------------------------------------------------
__device__ __forceinline__ float edge_weight(float4 vs, float4 vd,
                                             float4 ga, float4 gb) {
    float tx = vd.x - vs.x, ty = vd.y - vs.y, tz = vd.z - vs.z;
    // dist2 = tᵀ G t  (symmetric form)
    float dist2 = ga.x * tx * tx + ga.y * ty * ty + ga.z * tz * tz
                + 2.f * (ga.w * tx * ty + gb.x * tx * tz + gb.y * ty * tz);
    return __fdividef(1.f, 1.f + dist2);
}

// Edge pass 1 (4 edges/thread): w = 1/(1+dist²); scatter-add degrees.
__global__ __launch_bounds__(256) void edge_pass1_kernel(
    const int* __restrict__ src, const int* __restrict__ dst, int e)
{
    int i = (blockIdx.x * blockDim.x + threadIdx.x) * 4;
    if (i + 3 < e) {
        int4 s4 = *(const int4*)(src + i);
        int4 d4 = *(const int4*)(dst + i);
        int s[4] = {s4.x, s4.y, s4.z, s4.w};
        int d[4] = {d4.x, d4.y, d4.z, d4.w};
        float4 vs[4], vd[4], ga[4], gb[4];
        #pragma unroll
        for (int k = 0; k < 4; k++) {
            vs[k] = g_verts[s[k]];
            vd[k] = g_verts[d[k]];
            ga[k] = g_G[(size_t)s[k] * 2 + 0];
            gb[k] = g_G[(size_t)s[k] * 2 + 1];
        }
        float w[4];
        #pragma unroll
        for (int k = 0; k < 4; k++) w[k] = edge_weight(vs[k], vd[k], ga[k], gb[k]);
        *(float4*)(g_w + i) = make_float4(w[0], w[1], w[2], w[3]);
        #pragma unroll
        for (int k = 0; k < 4; k++) {
            atomicAdd(&g_row_sum[s[k]], w[k]);
            atomicAdd(&g_col_sum[d[k]], w[k]);
        }
    } else {
        for (; i < e; i++) {
            int s = src[i], d = dst[i];
            float w = edge_weight(g_verts[s], g_verts[d],
                                  g_G[(size_t)s * 2], g_G[(size_t)s * 2 + 1]);
            g_w[i] = w;
            atomicAdd(&g_row_sum[s], w);
            atomicAdd(&g_col_sum[d], w);
        }
    }
}

// ---------------------------------------------------------------------------
// Edge pass 2 (4 edges/thread): normalize + emit COO with streaming stores.
// mode 0: [rows(2E) | cols(2E) | values(2E)]. mode 1: values only (2E).
__global__ __launch_bounds__(256) void edge_pass2_kernel(
    const int* __restrict__ src, const int* __restrict__ dst,
    float* __restrict__ out, int e, int mode)
{
    int i = (blockIdx.x * blockDim.x + threadIdx.x) * 4;
    size_t E = (size_t)e;
    if (i + 3 < e) {
        int4 s4 = *(const int4*)(src + i);
        int4 d4 = *(const int4*)(dst + i);
        int s[4] = {s4.x, s4.y, s4.z, s4.w};
        int d[4] = {d4.x, d4.y, d4.z, d4.w};
        float4 w4 = *(const float4*)(g_w + i);
        float w[4] = {w4.x, w4.y, w4.z, w4.w};
        float irs[4], ics[4];
        #pragma unroll
        for (int k = 0; k < 4; k++) { irs[k] = g_row_sum[s[k]]; ics[k] = g_col_sum[d[k]]; }
        float4 vrow = make_float4(w[0]*irs[0], w[1]*irs[1], w[2]*irs[2], w[3]*irs[3]);
        float4 vcol = make_float4(w[0]*ics[0], w[1]*ics[1], w[2]*ics[2], w[3]*ics[3]);
        if (mode == 0) {
            float4 sf = make_float4(__int2float_rn(s[0]), __int2float_rn(s[1]),
                                    __int2float_rn(s[2]), __int2float_rn(s[3]));
            float4 df = make_float4(__int2float_rn(d[0]), __int2float_rn(d[1]),
                                    __int2float_rn(d[2]), __int2float_rn(d[3]));
            __stcs((float4*)(out + i), sf);           // rows[0:E]   = src
            __stcs((float4*)(out + E + i), df);       // rows[E:2E]  = dst
            __stcs((float4*)(out + 2*E + i), df);     // cols[0:E]   = dst
            __stcs((float4*)(out + 3*E + i), sf);     // cols[E:2E]  = src
            __stcs((float4*)(out + 4*E + i), vrow);   // values
            __stcs((float4*)(out + 5*E + i), vcol);
        } else {
            __stcs((float4*)(out + i), vrow);
            __stcs((float4*)(out + E + i), vcol);
        }
    } else {
        for (; i < e; i++) {
            int s = src[i], d = dst[i];
            float w = g_w[i];
            float vr = w * g_row_sum[s];
            float vc = w * g_col_sum[d];
            if (mode == 0) {
                out[i]         = (float)s;
                out[E + i]     = (float)d;
                out[2*E + i]   = (float)d;
                out[3*E + i]   = (float)s;
                out[4*E + i]   = vr;
                out[5*E + i]   = vc;
            } else {
                out[i]     = vr;
                out[E + i] = vc;
            }
        }
    }
}

// ---------------------------------------------------------------------------
extern "C" void kernel_launch(void* const* d_in, const int* in_sizes, int n_in,
                              void* d_out, int out_size)
{
    const float* features = (const float*)d_in[0];
    const float* vertices = (const float*)d_in[1];
    const float* W1       = (const float*)d_in[2];
    const float* b1       = (const float*)d_in[3];
    const float* W2       = (const float*)d_in[4];
    const float* b2       = (const float*)d_in[5];
    const int*   edges    = (const int*)  d_in[6];

    int n = in_sizes[1] / 3;   // vertices: (N, 3)
    int e = in_sizes[6] / 2;   // edges: (2, E)
    const int* src = edges;
    const int* dst = edges + e;
    float* out = (float*)d_out;

    int mode = (out_size == 2 * e) ? 1 : 0;

    int eq = (e + 3) / 4;
    zero_sums_kernel<<<(n + 255) / 256, 256>>>(n);
    mlp_kernel<<<(n + 127) / 128, 128>>>(features, vertices, W1, b1, W2, b2, n);
    edge_pass1_kernel<<<(eq + 255) / 256, 256>>>(src, dst, e);
    inv_sums_kernel<<<(n + 255) / 256, 256>>>(n);
    edge_pass2_kernel<<<(eq + 255) / 256, 256>>>(src, dst, out, e, mode);
}

// round 11
// speedup vs baseline: 1.1943x; 1.1790x over previous
#include <cuda_runtime.h>
#include <cuda_fp16.h>

// Problem-fixed maxima (N_VERTS=100000, N_EDGES=3200000)
#define NV_MAX 100000
#define E_MAX  3200000

// Per-vertex packed record, 32B:
//   rec[2v+0] = {vx, vy, vz, bits(half2(Gxx,Gyy))}
//   rec[2v+1] = {bits(half2(Gzz,Gxy)), bits(half2(Gxz,Gyz)), 0, 0}
__device__ float4 g_rec[NV_MAX * 2];
__device__ float  g_row_sum[NV_MAX];
__device__ float  g_col_sum[NV_MAX];
__device__ float  g_w[E_MAX];

// ---------------------------------------------------------------------------
// Per-vertex MLP: h = relu(f @ W1 + b1); M = h @ W2 + b2 (64 -> 32 -> 9),
// emit packed {v, G=MᵀM} record. Also zeroes the degree accumulators.
__global__ __launch_bounds__(128) void mlp_kernel(
    const float* __restrict__ features,
    const float* __restrict__ vertices,
    const float* __restrict__ W1,
    const float* __restrict__ b1,
    const float* __restrict__ W2,
    const float* __restrict__ b2,
    int n)
{
    __shared__ float feat_s[128 * 65];
    __shared__ float W1s[64 * 32];
    __shared__ float W2s[32 * 9];
    __shared__ float b1s[32];
    __shared__ float b2s[9];

    const int t  = threadIdx.x;
    const int v0 = blockIdx.x * 128;

    for (int i = t; i < 64 * 32; i += 128) W1s[i] = W1[i];
    for (int i = t; i < 32 * 9;  i += 128) W2s[i] = W2[i];
    if (t < 32) b1s[t] = b1[t];
    if (t < 9)  b2s[t] = b2[t];

    // Coalesced float4 load of the 128x64 feature tile (stride-65 padding)
    int nv = n - v0; if (nv > 128) nv = 128;
    const float4* fsrc = (const float4*)(features + (size_t)v0 * 64);
    int n4 = nv * 16;
    for (int i = t; i < n4; i += 128) {
        float4 f = fsrc[i];
        int row = i >> 4;
        int col = (i & 15) * 4;
        float* dstp = &feat_s[row * 65 + col];
        dstp[0] = f.x; dstp[1] = f.y; dstp[2] = f.z; dstp[3] = f.w;
    }
    __syncthreads();

    int v = v0 + t;
    if (v >= n) return;

    // zero accumulators (grid covers n)
    g_row_sum[v] = 0.f;
    g_col_sum[v] = 0.f;

    float h[32];
    #pragma unroll
    for (int j = 0; j < 32; j++) h[j] = b1s[j];

    const float* fr = &feat_s[t * 65];
    #pragma unroll 4
    for (int k = 0; k < 64; k++) {
        float fk = fr[k];
        #pragma unroll
        for (int j = 0; j < 32; j++) h[j] = fmaf(fk, W1s[k * 32 + j], h[j]);
    }
    #pragma unroll
    for (int j = 0; j < 32; j++) h[j] = fmaxf(h[j], 0.f);

    float m[9];
    #pragma unroll
    for (int c = 0; c < 9; c++) m[c] = b2s[c];
    #pragma unroll
    for (int j = 0; j < 32; j++) {
        float hj = h[j];
        #pragma unroll
        for (int c = 0; c < 9; c++) m[c] = fmaf(hj, W2s[j * 9 + c], m[c]);
    }

    // G = MᵀM (rows of M are m[3i..3i+2]); symmetric, 6 unique entries
    float Gxx = fmaf(m[0], m[0], fmaf(m[3], m[3], m[6] * m[6]));
    float Gyy = fmaf(m[1], m[1], fmaf(m[4], m[4], m[7] * m[7]));
    float Gzz = fmaf(m[2], m[2], fmaf(m[5], m[5], m[8] * m[8]));
    float Gxy = fmaf(m[0], m[1], fmaf(m[3], m[4], m[6] * m[7]));
    float Gxz = fmaf(m[0], m[2], fmaf(m[3], m[5], m[6] * m[8]));
    float Gyz = fmaf(m[1], m[2], fmaf(m[4], m[5], m[7] * m[8]));

    __half2 h01 = __floats2half2_rn(Gxx, Gyy);
    __half2 h23 = __floats2half2_rn(Gzz, Gxy);
    __half2 h45 = __floats2half2_rn(Gxz, Gyz);

    unsigned int u01 = *(unsigned int*)&h01;
    unsigned int u23 = *(unsigned int*)&h23;
    unsigned int u45 = *(unsigned int*)&h45;

    float vx = vertices[(size_t)v * 3 + 0];
    float vy = vertices[(size_t)v * 3 + 1];
    float vz = vertices[(size_t)v * 3 + 2];

    g_rec[(size_t)v * 2 + 0] = make_float4(vx, vy, vz, __uint_as_float(u01));
    g_rec[(size_t)v * 2 + 1] = make_float4(__uint_as_float(u23),
                                           __uint_as_float(u45), 0.f, 0.f);
}

// ---------------------------------------------------------------------------
__device__ __forceinline__ float edge_weight(const float4& r0s, const float2& r1s,
                                             const float4& r0d) {
    float tx = r0d.x - r0s.x, ty = r0d.y - r0s.y, tz = r0d.z - r0s.z;
    unsigned int u01 = __float_as_uint(r0s.w);
    unsigned int u23 = __float_as_uint(r1s.x);
    unsigned int u45 = __float_as_uint(r1s.y);
    float2 g01 = __half22float2(*(const __half2*)&u01);  // Gxx, Gyy
    float2 g23 = __half22float2(*(const __half2*)&u23);  // Gzz, Gxy
    float2 g45 = __half22float2(*(const __half2*)&u45);  // Gxz, Gyz
    float dist2 = g01.x * tx * tx + g01.y * ty * ty + g23.x * tz * tz
                + 2.f * (g23.y * tx * ty + g45.x * tx * tz + g45.y * ty * tz);
    return __fdividef(1.f, 1.f + dist2);
}

// Edge pass 1 (4 edges/thread): w = 1/(1+dist²); scatter-add degrees.
// Per-edge random ops: srcA(16B) + srcB(8B) + dstA(16B) + 2 atomics = 5.
__global__ __launch_bounds__(256) void edge_pass1_kernel(
    const int* __restrict__ src, const int* __restrict__ dst, int e)
{
    int i = (blockIdx.x * blockDim.x + threadIdx.x) * 4;
    if (i + 3 < e) {
        int4 s4 = *(const int4*)(src + i);
        int4 d4 = *(const int4*)(dst + i);
        int s[4] = {s4.x, s4.y, s4.z, s4.w};
        int d[4] = {d4.x, d4.y, d4.z, d4.w};
        float4 r0s[4], r0d[4];
        float2 r1s[4];
        #pragma unroll
        for (int k = 0; k < 4; k++) {
            r0s[k] = g_rec[(size_t)s[k] * 2 + 0];
            r1s[k] = *(const float2*)&g_rec[(size_t)s[k] * 2 + 1];
            r0d[k] = g_rec[(size_t)d[k] * 2 + 0];
        }
        float w[4];
        #pragma unroll
        for (int k = 0; k < 4; k++) w[k] = edge_weight(r0s[k], r1s[k], r0d[k]);
        *(float4*)(g_w + i) = make_float4(w[0], w[1], w[2], w[3]);
        #pragma unroll
        for (int k = 0; k < 4; k++) {
            atomicAdd(&g_row_sum[s[k]], w[k]);
            atomicAdd(&g_col_sum[d[k]], w[k]);
        }
    } else {
        for (; i < e; i++) {
            int s = src[i], d = dst[i];
            float4 r0s = g_rec[(size_t)s * 2 + 0];
            float2 r1s = *(const float2*)&g_rec[(size_t)s * 2 + 1];
            float4 r0d = g_rec[(size_t)d * 2 + 0];
            float w = edge_weight(r0s, r1s, r0d);
            g_w[i] = w;
            atomicAdd(&g_row_sum[s], w);
            atomicAdd(&g_col_sum[d], w);
        }
    }
}

// ---------------------------------------------------------------------------
// Edge pass 2 (4 edges/thread): normalize + emit COO with streaming stores.
// mode 0: [rows(2E) | cols(2E) | values(2E)]. mode 1: values only (2E).
__global__ __launch_bounds__(256) void edge_pass2_kernel(
    const int* __restrict__ src, const int* __restrict__ dst,
    float* __restrict__ out, int e, int mode)
{
    int i = (blockIdx.x * blockDim.x + threadIdx.x) * 4;
    size_t E = (size_t)e;
    if (i + 3 < e) {
        int4 s4 = *(const int4*)(src + i);
        int4 d4 = *(const int4*)(dst + i);
        int s[4] = {s4.x, s4.y, s4.z, s4.w};
        int d[4] = {d4.x, d4.y, d4.z, d4.w};
        float4 w4 = *(const float4*)(g_w + i);
        float w[4] = {w4.x, w4.y, w4.z, w4.w};
        float rs[4], cs[4];
        #pragma unroll
        for (int k = 0; k < 4; k++) { rs[k] = g_row_sum[s[k]]; cs[k] = g_col_sum[d[k]]; }
        float4 vrow, vcol;
        vrow.x = __fdividef(0.5f * w[0], rs[0]);
        vrow.y = __fdividef(0.5f * w[1], rs[1]);
        vrow.z = __fdividef(0.5f * w[2], rs[2]);
        vrow.w = __fdividef(0.5f * w[3], rs[3]);
        vcol.x = __fdividef(0.5f * w[0], cs[0]);
        vcol.y = __fdividef(0.5f * w[1], cs[1]);
        vcol.z = __fdividef(0.5f * w[2], cs[2]);
        vcol.w = __fdividef(0.5f * w[3], cs[3]);
        if (mode == 0) {
            float4 sf = make_float4(__int2float_rn(s[0]), __int2float_rn(s[1]),
                                    __int2float_rn(s[2]), __int2float_rn(s[3]));
            float4 df = make_float4(__int2float_rn(d[0]), __int2float_rn(d[1]),
                                    __int2float_rn(d[2]), __int2float_rn(d[3]));
            __stcs((float4*)(out + i), sf);           // rows[0:E]   = src
            __stcs((float4*)(out + E + i), df);       // rows[E:2E]  = dst
            __stcs((float4*)(out + 2*E + i), df);     // cols[0:E]   = dst
            __stcs((float4*)(out + 3*E + i), sf);     // cols[E:2E]  = src
            __stcs((float4*)(out + 4*E + i), vrow);   // values
            __stcs((float4*)(out + 5*E + i), vcol);
        } else {
            __stcs((float4*)(out + i), vrow);
            __stcs((float4*)(out + E + i), vcol);
        }
    } else {
        for (; i < e; i++) {
            int s = src[i], d = dst[i];
            float w = g_w[i];
            float vr = __fdividef(0.5f * w, g_row_sum[s]);
            float vc = __fdividef(0.5f * w, g_col_sum[d]);
            if (mode == 0) {
                out[i]       = (float)s;
                out[E + i]   = (float)d;
                out[2*E + i] = (float)d;
                out[3*E + i] = (float)s;
                out[4*E + i] = vr;
                out[5*E + i] = vc;
            } else {
                out[i]     = vr;
                out[E + i] = vc;
            }
        }
    }
}

// ---------------------------------------------------------------------------
extern "C" void kernel_launch(void* const* d_in, const int* in_sizes, int n_in,
                              void* d_out, int out_size)
{
    const float* features = (const float*)d_in[0];
    const float* vertices = (const float*)d_in[1];
    const float* W1       = (const float*)d_in[2];
    const float* b1       = (const float*)d_in[3];
    const float* W2       = (const float*)d_in[4];
    const float* b2       = (const float*)d_in[5];
    const int*   edges    = (const int*)  d_in[6];

    int n = in_sizes[1] / 3;   // vertices: (N, 3)
    int e = in_sizes[6] / 2;   // edges: (2, E)
    const int* src = edges;
    const int* dst = edges + e;
    float* out = (float*)d_out;

    int mode = (out_size == 2 * e) ? 1 : 0;

    int eq = (e + 3) / 4;
    mlp_kernel<<<(n + 127) / 128, 128>>>(features, vertices, W1, b1, W2, b2, n);
    edge_pass1_kernel<<<(eq + 255) / 256, 256>>>(src, dst, e);
    edge_pass2_kernel<<<(eq + 255) / 256, 256>>>(src, dst, out, e, mode);
}